// round 14
// baseline (speedup 1.0000x reference)
#include <cuda_runtime.h>
#include <cuda_fp16.h>
#include <cstdint>
#include <math.h>

// ============================================================================
// VisionExperts, Round 11: R10 linear collapse +
//  (1) parallel bias_comb (block-per-n reduction; was 79us x3 serial),
//  (2) fused dual resize_combine (one RMW sweep of out instead of two),
//  (3) e2 chain on its own stream (s2) concurrent with e1 chain (s1).
// ============================================================================

// ---------------- scratch (device globals; no allocs) ----------------
__device__ float g_gate[3 * 64];
__device__ float g_one[1];
__device__ float g_zb[3072];                          // zero bias (static zero-init)
__device__ float g_x336[21676032];
__device__ float g_proj1[37748736];                   // e1 projected (36864x1024)
__device__ float g_proj2[12845056];                   // e2 projected (12544x1024)
__device__ float g_bc0[1024], g_bc1[1024], g_bc2[1024];
__device__ __align__(128) __half g_A1_0[41943040];    // 65536 x 640
__device__ __align__(128) __half g_A1_1[23592960];    // 36864 x 640
__device__ __align__(128) __half g_A1_2[38535168];    // 12544 x 3072
__device__ __align__(128) __half g_WpT0[1048576];     // 1024 x 1024
__device__ __align__(128) __half g_WpT1[786432];      // 1024 x 768
__device__ __align__(128) __half g_WpT2[1179648];     // 1024 x 1152
__device__ __align__(128) __half g_WtC0[655360];      // 640 x 1024
__device__ __align__(128) __half g_WtC1[491520];      // 640 x 768
__device__ __align__(128) __half g_WtC2[3538944];     // 3072 x 1152
__device__ __align__(128) __half g_Bc0[655360];       // Bcomb0: 1024 x 640
__device__ __align__(128) __half g_Bc1[655360];       // Bcomb1: 1024 x 640
__device__ __align__(128) __half g_Bc2[3145728];      // Bcomb2: 1024 x 3072

// ---------------- helpers ----------------
__device__ __forceinline__ uint32_t smem_u32(const void* p) {
    uint32_t a;
    asm("{ .reg .u64 t; cvta.to.shared.u64 t, %1; cvt.u32.u64 %0, t; }" : "=r"(a) : "l"(p));
    return a;
}
__device__ __forceinline__ void cp16(uint32_t so, const void* g) {
    asm volatile("cp.async.cg.shared.global [%0], [%1], 16;" :: "r"(so), "l"(g));
}
__device__ __forceinline__ void ldm4(uint32_t* r, uint32_t addr) {
    asm volatile("ldmatrix.sync.aligned.m8n8.x4.shared.b16 {%0,%1,%2,%3}, [%4];"
                 : "=r"(r[0]), "=r"(r[1]), "=r"(r[2]), "=r"(r[3]) : "r"(addr));
}
__device__ __forceinline__ void mma_f16(float* d, const uint32_t* a, uint32_t b0, uint32_t b1) {
    asm volatile("mma.sync.aligned.m16n8k16.row.col.f32.f16.f16.f32 "
                 "{%0,%1,%2,%3}, {%4,%5,%6,%7}, {%8,%9}, {%0,%1,%2,%3};"
                 : "+f"(d[0]), "+f"(d[1]), "+f"(d[2]), "+f"(d[3])
                 : "r"(a[0]), "r"(a[1]), "r"(a[2]), "r"(a[3]), "r"(b0), "r"(b1));
}

// ---------------- gates ----------------
__global__ void gate_kernel(const int* __restrict__ sel, const float* __restrict__ rw) {
    int b = threadIdx.x;
    if (b == 0) g_one[0] = 1.f;
    if (b >= 64) return;
    float w0 = 0.f, w1 = 0.f, w2 = 0.f;
#pragma unroll
    for (int k = 0; k < 2; k++) {
        int e = sel[b * 2 + k];
        float r = rw[b * 2 + k];
        w0 += (e == 0) ? r : 0.f;
        w1 += (e == 1) ? r : 0.f;
        w2 += (e == 2) ? r : 0.f;
    }
    g_gate[b] = w0; g_gate[64 + b] = w1; g_gate[128 + b] = w2;
}

// ---------------- input resize 448 -> 336 ----------------
__global__ void resize_input_kernel(const float* __restrict__ x) {
    long long idx = (long long)blockIdx.x * blockDim.x + threadIdx.x;
    const long long total = 64LL * 3 * 336 * 336;
    if (idx >= total) return;
    int ox = (int)(idx % 336);
    long long r = idx / 336;
    int oy = (int)(r % 336); r /= 336;
    int c = (int)(r % 3);
    int b = (int)(r / 3);
    if (g_gate[64 + b] == 0.f) return;
    const float sc = 447.0f / 335.0f;
    float ys = oy * sc, xs = ox * sc;
    int y0 = (int)floorf(ys); int y1 = min(y0 + 1, 447);
    int x0 = (int)floorf(xs); int x1 = min(x0 + 1, 447);
    float ty = ys - (float)y0, tx = xs - (float)x0;
    const float* p = x + ((long long)(b * 3 + c)) * 448 * 448;
    float a = p[y0 * 448 + x0], bv = p[y0 * 448 + x1];
    float cv = p[y1 * 448 + x0], dv = p[y1 * 448 + x1];
    float r0 = a * (1.f - ty) + cv * ty;
    float r1 = bv * (1.f - ty) + dv * ty;
    g_x336[idx] = r0 * (1.f - tx) + r1 * tx;
}

// ---------------- weight transpose: W[K,N] -> B[N,Kp] fp16 ----------------
__global__ void weight_halfT(const float* __restrict__ W, int K, int N, int Kp,
                             __half* __restrict__ B) {
    long long idx = (long long)blockIdx.x * blockDim.x + threadIdx.x;
    long long total = (long long)N * Kp;
    if (idx >= total) return;
    int k = (int)(idx % Kp);
    int n = (int)(idx / Kp);
    float v = (k < K) ? W[(long long)k * N + n] : 0.f;
    B[idx] = __float2half_rn(v);
}

// ---------------- weight row-cast (no transpose): W[Kreal,C] -> [Kpad,C] ----
__global__ void weight_cast(const float* __restrict__ W, int Kreal, int Kpad, int C,
                            __half* __restrict__ O) {
    long long idx = (long long)blockIdx.x * blockDim.x + threadIdx.x;
    long long total = (long long)Kpad * C;
    if (idx >= total) return;
    int c = (int)(idx % C);
    int k = (int)(idx / C);
    O[idx] = __float2half_rn((k < Kreal) ? W[(long long)k * C + c] : 0.f);
}

// ---------------- combined bias (block-per-n): bc[n] = bp[n] + bt . wp[:,n] -
__global__ void bias_comb(const float* __restrict__ bt, const float* __restrict__ wp,
                          const float* __restrict__ bp, int C, float* __restrict__ bc) {
    const int n = blockIdx.x;            // 1024 blocks
    const int tid = threadIdx.x;         // 256 threads
    float s = 0.f;
    for (int c = tid; c < C; c += 256) s += bt[c] * wp[(long long)c * 1024 + n];
#pragma unroll
    for (int o = 16; o > 0; o >>= 1) s += __shfl_down_sync(0xFFFFFFFFu, s, o);
    __shared__ float red[8];
    if ((tid & 31) == 0) red[tid >> 5] = s;
    __syncthreads();
    if (tid == 0) {
        float t = 0.f;
#pragma unroll
        for (int i = 0; i < 8; i++) t += red[i];
        bc[n] = t + bp[n];
    }
}

// ---------------- im2col -> fp16 (templated; 8 elems/thread) ----------------
template <int S, int P, int G, int KP>
__global__ void im2col_half(const float* __restrict__ src, const float* __restrict__ gate,
                            __half* __restrict__ A) {
    constexpr int K = 3 * P * P;
    constexpr int GG = G * G;
    long long v8 = (long long)blockIdx.x * blockDim.x + threadIdx.x;
    const long long total8 = 64LL * GG * (KP / 8);
    if (v8 >= total8) return;
    int kc = (int)(v8 % (KP / 8));
    long long row = v8 / (KP / 8);
    int t = (int)(row % GG);
    int b = (int)(row / GG);
    if (gate[b] == 0.f) return;
    const int ty = t / G, tx = t % G;
    const float* sb = src + ((long long)b * 3) * S * S;
    __half h[8];
#pragma unroll
    for (int j = 0; j < 8; j++) {
        int k = kc * 8 + j;
        float v = 0.f;
        if (k < K) {
            int ch = k / (P * P);
            int rr = k - ch * (P * P);
            int py = rr / P, px = rr - py * P;
            v = sb[((long long)ch * S + (ty * P + py)) * S + (tx * P + px)];
        }
        h[j] = __float2half_rn(v);
    }
    *reinterpret_cast<uint4*>(&A[row * KP + kc * 8]) = *reinterpret_cast<uint4*>(h);
}

// ---------------- fused dual gated bilinear combine into out ----------------
// out[b*1024+ot,:] += w1*interp_G1(proj1) + w2*interp_G2(proj2), one RMW sweep.
template <int G1, int G2>
__global__ void resize_combine2(const float* __restrict__ proj1, const float* __restrict__ proj2,
                                const float* __restrict__ gate1, const float* __restrict__ gate2,
                                float* __restrict__ out) {
    long long idx = (long long)blockIdx.x * blockDim.x + threadIdx.x;
    const long long total = 64LL * 1024 * 256;     // float4 granularity
    if (idx >= total) return;
    int cc = (int)(idx & 255);
    long long r = idx >> 8;
    int ot = (int)(r & 1023);
    int b = (int)(r >> 10);
    float w1 = gate1[b], w2 = gate2[b];
    if (w1 == 0.f && w2 == 0.f) return;
    int oy = ot >> 5, ox = ot & 31;
    float4 acc = make_float4(0.f, 0.f, 0.f, 0.f);
    if (w1 != 0.f) {
        const float sc = (float)(G1 - 1) / 31.0f;
        float ys = oy * sc, xs = ox * sc;
        int y0 = (int)floorf(ys); int y1 = min(y0 + 1, G1 - 1);
        int x0 = (int)floorf(xs); int x1 = min(x0 + 1, G1 - 1);
        float ty = ys - (float)y0, tx = xs - (float)x0;
        const float* pb = proj1 + (long long)b * G1 * G1 * 1024 + cc * 4;
        float4 a = *reinterpret_cast<const float4*>(pb + (long long)(y0 * G1 + x0) * 1024);
        float4 bv = *reinterpret_cast<const float4*>(pb + (long long)(y0 * G1 + x1) * 1024);
        float4 cv = *reinterpret_cast<const float4*>(pb + (long long)(y1 * G1 + x0) * 1024);
        float4 dv = *reinterpret_cast<const float4*>(pb + (long long)(y1 * G1 + x1) * 1024);
        float r0, r1;
        r0 = a.x * (1.f - ty) + cv.x * ty; r1 = bv.x * (1.f - ty) + dv.x * ty;
        acc.x += w1 * (r0 * (1.f - tx) + r1 * tx);
        r0 = a.y * (1.f - ty) + cv.y * ty; r1 = bv.y * (1.f - ty) + dv.y * ty;
        acc.y += w1 * (r0 * (1.f - tx) + r1 * tx);
        r0 = a.z * (1.f - ty) + cv.z * ty; r1 = bv.z * (1.f - ty) + dv.z * ty;
        acc.z += w1 * (r0 * (1.f - tx) + r1 * tx);
        r0 = a.w * (1.f - ty) + cv.w * ty; r1 = bv.w * (1.f - ty) + dv.w * ty;
        acc.w += w1 * (r0 * (1.f - tx) + r1 * tx);
    }
    if (w2 != 0.f) {
        const float sc = (float)(G2 - 1) / 31.0f;
        float ys = oy * sc, xs = ox * sc;
        int y0 = (int)floorf(ys); int y1 = min(y0 + 1, G2 - 1);
        int x0 = (int)floorf(xs); int x1 = min(x0 + 1, G2 - 1);
        float ty = ys - (float)y0, tx = xs - (float)x0;
        const float* pb = proj2 + (long long)b * G2 * G2 * 1024 + cc * 4;
        float4 a = *reinterpret_cast<const float4*>(pb + (long long)(y0 * G2 + x0) * 1024);
        float4 bv = *reinterpret_cast<const float4*>(pb + (long long)(y0 * G2 + x1) * 1024);
        float4 cv = *reinterpret_cast<const float4*>(pb + (long long)(y1 * G2 + x0) * 1024);
        float4 dv = *reinterpret_cast<const float4*>(pb + (long long)(y1 * G2 + x1) * 1024);
        float r0, r1;
        r0 = a.x * (1.f - ty) + cv.x * ty; r1 = bv.x * (1.f - ty) + dv.x * ty;
        acc.x += w2 * (r0 * (1.f - tx) + r1 * tx);
        r0 = a.y * (1.f - ty) + cv.y * ty; r1 = bv.y * (1.f - ty) + dv.y * ty;
        acc.y += w2 * (r0 * (1.f - tx) + r1 * tx);
        r0 = a.z * (1.f - ty) + cv.z * ty; r1 = bv.z * (1.f - ty) + dv.z * ty;
        acc.z += w2 * (r0 * (1.f - tx) + r1 * tx);
        r0 = a.w * (1.f - ty) + cv.w * ty; r1 = bv.w * (1.f - ty) + dv.w * ty;
        acc.w += w2 * (r0 * (1.f - tx) + r1 * tx);
    }
    float* op = out + ((long long)(b * 1024 + ot)) * 1024 + cc * 4;
    float4 o = *reinterpret_cast<const float4*>(op);
    o.x += acc.x; o.y += acc.y; o.z += acc.z; o.w += acc.w;
    *reinterpret_cast<float4*>(op) = o;
}

// ---------------- HMMA GEMM: C = A @ B^T, fp32 accumulate ------------------
// 128x128 CTA tile, warp tile 64x32, K-chunk 64, 3-stage cp.async pipeline.
// outmode 0: outF = acc + bias   1: outF += gate*(acc+bias)   2: outH fp16
__global__ void __launch_bounds__(256) gemm_mma(
    const __half* __restrict__ A, const __half* __restrict__ B,
    const float* __restrict__ bias, int N, int Kp,
    const float* __restrict__ gate, int gg, int outmode,
    float* __restrict__ outF, __half* __restrict__ outH)
{
    const int row0 = blockIdx.y * 128;
    const int col0 = blockIdx.x * 128;
    {   // gated tile skip
        int b0 = row0 / gg, b1 = (row0 + 127) / gg;
        float gm = 0.f;
        for (int b = b0; b <= b1; b++) gm = fmaxf(gm, gate[b]);
        if (gm == 0.f) return;
    }

    extern __shared__ char smem[];
    const uint32_t S = smem_u32(smem);
    const int tid = threadIdx.x;
    const int wid = tid >> 5, lane = tid & 31;
    const int wm = (wid >> 2) * 64;
    const int wn = (wid & 3) * 32;
    const int NC = Kp >> 6;

    auto prefetch = [&](int c) {
        uint32_t st = S + (uint32_t)(c % 3) * 32768u;
        int kt = c << 6;
#pragma unroll
        for (int i = 0; i < 8; i++) {
            int cid = tid + (i << 8);
            int isB = cid >> 10;
            int rem = cid & 1023;
            int r = rem >> 3, j = rem & 7;
            const __half* gp = (!isB ? A + (size_t)(row0 + r) * Kp
                                     : B + (size_t)(col0 + r) * Kp) + kt + j * 8;
            uint32_t so = st + (isB << 14) + r * 128 + ((j ^ (r & 7)) << 4);
            cp16(so, gp);
        }
        asm volatile("cp.async.commit_group;" ::: "memory");
    };

    float acc[4][4][4];
#pragma unroll
    for (int i = 0; i < 4; i++)
#pragma unroll
        for (int j = 0; j < 4; j++)
#pragma unroll
            for (int q = 0; q < 4; q++) acc[i][j][q] = 0.f;

    const int lrow = lane & 15;
    const int lchunk = lane >> 4;

    prefetch(0);
    if (NC > 1) prefetch(1);
    for (int c = 0; c < NC; c++) {
        if (c + 2 < NC) {
            prefetch(c + 2);
            asm volatile("cp.async.wait_group 2;" ::: "memory");
        } else if (c + 1 < NC) {
            asm volatile("cp.async.wait_group 1;" ::: "memory");
        } else {
            asm volatile("cp.async.wait_group 0;" ::: "memory");
        }
        __syncthreads();

        uint32_t SA = S + (uint32_t)(c % 3) * 32768u;
        uint32_t SB = SA + 16384u;

#pragma unroll
        for (int k = 0; k < 4; k++) {
            const int ch = 2 * k + lchunk;
            uint32_t b[2][4];
#pragma unroll
            for (int j2 = 0; j2 < 2; j2++) {
                int rb = wn + j2 * 16 + lrow;
                ldm4(b[j2], SB + rb * 128 + ((ch ^ (rb & 7)) << 4));
            }
#pragma unroll
            for (int i = 0; i < 4; i++) {
                int ra = wm + i * 16 + lrow;
                uint32_t a[4];
                ldm4(a, SA + ra * 128 + ((ch ^ (ra & 7)) << 4));
#pragma unroll
                for (int j2 = 0; j2 < 2; j2++) {
                    mma_f16(acc[i][2 * j2],     a, b[j2][0], b[j2][2]);
                    mma_f16(acc[i][2 * j2 + 1], a, b[j2][1], b[j2][3]);
                }
            }
        }
        __syncthreads();
    }

    // ---- epilogue ----
    const int grp = lane >> 2, qid = lane & 3;
#pragma unroll
    for (int i = 0; i < 4; i++) {
        int r0 = row0 + wm + i * 16 + grp;
        int r1 = r0 + 8;
#pragma unroll
        for (int j = 0; j < 4; j++) {
            int col = col0 + wn + j * 8 + qid * 2;
            float b0 = bias[col], b1 = bias[col + 1];
            float v00 = acc[i][j][0] + b0, v01 = acc[i][j][1] + b1;
            float v10 = acc[i][j][2] + b0, v11 = acc[i][j][3] + b1;
            if (outmode == 0) {
                *reinterpret_cast<float2*>(&outF[(size_t)r0 * N + col]) = make_float2(v00, v01);
                *reinterpret_cast<float2*>(&outF[(size_t)r1 * N + col]) = make_float2(v10, v11);
            } else if (outmode == 1) {
                float w0 = gate[r0 / gg], w1 = gate[r1 / gg];
                if (w0 != 0.f) {
                    float2 o = *reinterpret_cast<const float2*>(&outF[(size_t)r0 * N + col]);
                    o.x += w0 * v00; o.y += w0 * v01;
                    *reinterpret_cast<float2*>(&outF[(size_t)r0 * N + col]) = o;
                }
                if (w1 != 0.f) {
                    float2 o = *reinterpret_cast<const float2*>(&outF[(size_t)r1 * N + col]);
                    o.x += w1 * v10; o.y += w1 * v11;
                    *reinterpret_cast<float2*>(&outF[(size_t)r1 * N + col]) = o;
                }
            } else {
                __half2 hp;
                hp.x = __float2half_rn(v00); hp.y = __float2half_rn(v01);
                *reinterpret_cast<__half2*>(&outH[(size_t)r0 * N + col]) = hp;
                hp.x = __float2half_rn(v10); hp.y = __float2half_rn(v11);
                *reinterpret_cast<__half2*>(&outH[(size_t)r1 * N + col]) = hp;
            }
        }
    }
}

// ---------------- launch ----------------
static inline int nblk(long long total, int t) { return (int)((total + t - 1) / t); }

extern "C" void kernel_launch(void* const* d_in, const int* in_sizes, int n_in,
                              void* d_out, int out_size) {
    const float* x   = (const float*)d_in[0];
    const int*   sel = (const int*)d_in[1];
    const float* rw  = (const float*)d_in[2];
    const float* wt0 = (const float*)d_in[3];  const float* bt0 = (const float*)d_in[4];
    const float* wp0 = (const float*)d_in[5];  const float* bp0 = (const float*)d_in[6];
    const float* wt1 = (const float*)d_in[7];  const float* bt1 = (const float*)d_in[8];
    const float* wp1 = (const float*)d_in[9];  const float* bp1 = (const float*)d_in[10];
    const float* wt2 = (const float*)d_in[11]; const float* bt2 = (const float*)d_in[12];
    const float* wp2 = (const float*)d_in[13]; const float* bp2 = (const float*)d_in[14];
    float* out = (float*)d_out;

    float *gate_d, *one_d, *zb_d, *x336_d, *proj1_d, *proj2_d, *bc0_d, *bc1_d, *bc2_d;
    __half *A10, *A11, *A12, *WpT0, *WpT1, *WpT2, *WtC0, *WtC1, *WtC2, *Bc0, *Bc1, *Bc2;
    cudaGetSymbolAddress((void**)&gate_d, g_gate);
    cudaGetSymbolAddress((void**)&one_d, g_one);
    cudaGetSymbolAddress((void**)&zb_d, g_zb);
    cudaGetSymbolAddress((void**)&x336_d, g_x336);
    cudaGetSymbolAddress((void**)&proj1_d, g_proj1);
    cudaGetSymbolAddress((void**)&proj2_d, g_proj2);
    cudaGetSymbolAddress((void**)&bc0_d, g_bc0);
    cudaGetSymbolAddress((void**)&bc1_d, g_bc1);
    cudaGetSymbolAddress((void**)&bc2_d, g_bc2);
    cudaGetSymbolAddress((void**)&A10, g_A1_0);
    cudaGetSymbolAddress((void**)&A11, g_A1_1);
    cudaGetSymbolAddress((void**)&A12, g_A1_2);
    cudaGetSymbolAddress((void**)&WpT0, g_WpT0);
    cudaGetSymbolAddress((void**)&WpT1, g_WpT1);
    cudaGetSymbolAddress((void**)&WpT2, g_WpT2);
    cudaGetSymbolAddress((void**)&WtC0, g_WtC0);
    cudaGetSymbolAddress((void**)&WtC1, g_WtC1);
    cudaGetSymbolAddress((void**)&WtC2, g_WtC2);
    cudaGetSymbolAddress((void**)&Bc0, g_Bc0);
    cudaGetSymbolAddress((void**)&Bc1, g_Bc1);
    cudaGetSymbolAddress((void**)&Bc2, g_Bc2);

    static cudaStream_t s1 = nullptr, s2 = nullptr;
    static cudaEvent_t evG = nullptr, evC0 = nullptr, evP1 = nullptr, evP2 = nullptr;
    if (s1 == nullptr) {
        cudaStreamCreateWithFlags(&s1, cudaStreamNonBlocking);
        cudaStreamCreateWithFlags(&s2, cudaStreamNonBlocking);
        cudaEventCreateWithFlags(&evG, cudaEventDisableTiming);
        cudaEventCreateWithFlags(&evC0, cudaEventDisableTiming);
        cudaEventCreateWithFlags(&evP1, cudaEventDisableTiming);
        cudaEventCreateWithFlags(&evP2, cudaEventDisableTiming);
    }

    const int SMEM = 3 * 32768;
    cudaFuncSetAttribute(gemm_mma, cudaFuncAttributeMaxDynamicSharedMemorySize, SMEM);
    const int BIGG = 1 << 30;

    // ---- main: gates, memset; fork side streams ----
    gate_kernel<<<1, 64>>>(sel, rw);
    cudaEventRecord(evG, 0);
    cudaMemsetAsync(d_out, 0, (size_t)out_size * sizeof(float));

    // ---- s1: e0 combined-weight prep, then e1 chain ----
    cudaStreamWaitEvent(s1, evG, 0);
    weight_halfT<<<nblk(1024LL * 1024, 256), 256, 0, s1>>>(wp0, 1024, 1024, 1024, WpT0);
    weight_cast<<<nblk(640LL * 1024, 256), 256, 0, s1>>>(wt0, 588, 640, 1024, WtC0);
    bias_comb<<<1024, 256, 0, s1>>>(bt0, wp0, bp0, 1024, bc0_d);
    gemm_mma<<<dim3(5, 8), 256, SMEM, s1>>>(WpT0, WtC0, zb_d, 640, 1024,
                                            one_d, BIGG, 2, nullptr, Bc0);
    cudaEventRecord(evC0, s1);
    weight_halfT<<<nblk(1024LL * 768, 256), 256, 0, s1>>>(wp1, 768, 1024, 768, WpT1);
    weight_cast<<<nblk(640LL * 768, 256), 256, 0, s1>>>(wt1, 588, 640, 768, WtC1);
    bias_comb<<<1024, 256, 0, s1>>>(bt1, wp1, bp1, 768, bc1_d);
    gemm_mma<<<dim3(5, 8), 256, SMEM, s1>>>(WpT1, WtC1, zb_d, 640, 768,
                                            one_d, BIGG, 2, nullptr, Bc1);
    resize_input_kernel<<<nblk(64LL * 3 * 336 * 336, 256), 256, 0, s1>>>(x);
    im2col_half<336, 14, 24, 640><<<nblk(64LL * 576 * 80, 256), 256, 0, s1>>>(x336_d, gate_d + 64, A11);
    gemm_mma<<<dim3(8, 288), 256, SMEM, s1>>>(A11, Bc1, bc1_d, 1024, 640,
                                              gate_d + 64, 576, 0, proj1_d, nullptr);
    cudaEventRecord(evP1, s1);

    // ---- s2: e2 chain ----
    cudaStreamWaitEvent(s2, evG, 0);
    weight_halfT<<<nblk(1024LL * 1152, 256), 256, 0, s2>>>(wp2, 1152, 1024, 1152, WpT2);
    weight_cast<<<nblk(3072LL * 1152, 256), 256, 0, s2>>>(wt2, 3072, 3072, 1152, WtC2);
    bias_comb<<<1024, 256, 0, s2>>>(bt2, wp2, bp2, 1152, bc2_d);
    gemm_mma<<<dim3(24, 8), 256, SMEM, s2>>>(WpT2, WtC2, zb_d, 3072, 1152,
                                             one_d, BIGG, 2, nullptr, Bc2);
    im2col_half<448, 32, 14, 3072><<<nblk(64LL * 196 * 384, 256), 256, 0, s2>>>(x, gate_d + 128, A12);
    gemm_mma<<<dim3(8, 98), 256, SMEM, s2>>>(A12, Bc2, bc2_d, 1024, 3072,
                                             gate_d + 128, 196, 0, proj2_d, nullptr);
    cudaEventRecord(evP2, s2);

    // ---- main: e0 single GEMM into out, then fused combine ----
    im2col_half<448, 14, 32, 640><<<nblk(64LL * 1024 * 80, 256), 256>>>(x, gate_d, A10);
    cudaStreamWaitEvent(0, evC0, 0);
    gemm_mma<<<dim3(8, 512), 256, SMEM>>>(A10, Bc0, bc0_d, 1024, 640,
                                          gate_d, 1024, 1, out, nullptr);
    cudaStreamWaitEvent(0, evP1, 0);
    cudaStreamWaitEvent(0, evP2, 0);
    resize_combine2<24, 14><<<nblk(64LL * 1024 * 256, 256), 256>>>(
        proj1_d, proj2_d, gate_d + 64, gate_d + 128, out);
}

// round 15
// speedup vs baseline: 1.0006x; 1.0006x over previous
#include <cuda_runtime.h>
#include <cuda_fp16.h>
#include <cstdint>
#include <math.h>

// ============================================================================
// VisionExperts, Round 11: R10 linear collapse +
//  (1) parallel bias_comb (block-per-n reduction; was 79us x3 serial),
//  (2) fused dual resize_combine (one RMW sweep of out instead of two),
//  (3) e2 chain on its own stream (s2) concurrent with e1 chain (s1).
// ============================================================================

// ---------------- scratch (device globals; no allocs) ----------------
__device__ float g_gate[3 * 64];
__device__ float g_one[1];
__device__ float g_zb[3072];                          // zero bias (static zero-init)
__device__ float g_x336[21676032];
__device__ float g_proj1[37748736];                   // e1 projected (36864x1024)
__device__ float g_proj2[12845056];                   // e2 projected (12544x1024)
__device__ float g_bc0[1024], g_bc1[1024], g_bc2[1024];
__device__ __align__(128) __half g_A1_0[41943040];    // 65536 x 640
__device__ __align__(128) __half g_A1_1[23592960];    // 36864 x 640
__device__ __align__(128) __half g_A1_2[38535168];    // 12544 x 3072
__device__ __align__(128) __half g_WpT0[1048576];     // 1024 x 1024
__device__ __align__(128) __half g_WpT1[786432];      // 1024 x 768
__device__ __align__(128) __half g_WpT2[1179648];     // 1024 x 1152
__device__ __align__(128) __half g_WtC0[655360];      // 640 x 1024
__device__ __align__(128) __half g_WtC1[491520];      // 640 x 768
__device__ __align__(128) __half g_WtC2[3538944];     // 3072 x 1152
__device__ __align__(128) __half g_Bc0[655360];       // Bcomb0: 1024 x 640
__device__ __align__(128) __half g_Bc1[655360];       // Bcomb1: 1024 x 640
__device__ __align__(128) __half g_Bc2[3145728];      // Bcomb2: 1024 x 3072

// ---------------- helpers ----------------
__device__ __forceinline__ uint32_t smem_u32(const void* p) {
    uint32_t a;
    asm("{ .reg .u64 t; cvta.to.shared.u64 t, %1; cvt.u32.u64 %0, t; }" : "=r"(a) : "l"(p));
    return a;
}
__device__ __forceinline__ void cp16(uint32_t so, const void* g) {
    asm volatile("cp.async.cg.shared.global [%0], [%1], 16;" :: "r"(so), "l"(g));
}
__device__ __forceinline__ void ldm4(uint32_t* r, uint32_t addr) {
    asm volatile("ldmatrix.sync.aligned.m8n8.x4.shared.b16 {%0,%1,%2,%3}, [%4];"
                 : "=r"(r[0]), "=r"(r[1]), "=r"(r[2]), "=r"(r[3]) : "r"(addr));
}
__device__ __forceinline__ void mma_f16(float* d, const uint32_t* a, uint32_t b0, uint32_t b1) {
    asm volatile("mma.sync.aligned.m16n8k16.row.col.f32.f16.f16.f32 "
                 "{%0,%1,%2,%3}, {%4,%5,%6,%7}, {%8,%9}, {%0,%1,%2,%3};"
                 : "+f"(d[0]), "+f"(d[1]), "+f"(d[2]), "+f"(d[3])
                 : "r"(a[0]), "r"(a[1]), "r"(a[2]), "r"(a[3]), "r"(b0), "r"(b1));
}

// ---------------- gates ----------------
__global__ void gate_kernel(const int* __restrict__ sel, const float* __restrict__ rw) {
    int b = threadIdx.x;
    if (b == 0) g_one[0] = 1.f;
    if (b >= 64) return;
    float w0 = 0.f, w1 = 0.f, w2 = 0.f;
#pragma unroll
    for (int k = 0; k < 2; k++) {
        int e = sel[b * 2 + k];
        float r = rw[b * 2 + k];
        w0 += (e == 0) ? r : 0.f;
        w1 += (e == 1) ? r : 0.f;
        w2 += (e == 2) ? r : 0.f;
    }
    g_gate[b] = w0; g_gate[64 + b] = w1; g_gate[128 + b] = w2;
}

// ---------------- input resize 448 -> 336 ----------------
__global__ void resize_input_kernel(const float* __restrict__ x) {
    long long idx = (long long)blockIdx.x * blockDim.x + threadIdx.x;
    const long long total = 64LL * 3 * 336 * 336;
    if (idx >= total) return;
    int ox = (int)(idx % 336);
    long long r = idx / 336;
    int oy = (int)(r % 336); r /= 336;
    int c = (int)(r % 3);
    int b = (int)(r / 3);
    if (g_gate[64 + b] == 0.f) return;
    const float sc = 447.0f / 335.0f;
    float ys = oy * sc, xs = ox * sc;
    int y0 = (int)floorf(ys); int y1 = min(y0 + 1, 447);
    int x0 = (int)floorf(xs); int x1 = min(x0 + 1, 447);
    float ty = ys - (float)y0, tx = xs - (float)x0;
    const float* p = x + ((long long)(b * 3 + c)) * 448 * 448;
    float a = p[y0 * 448 + x0], bv = p[y0 * 448 + x1];
    float cv = p[y1 * 448 + x0], dv = p[y1 * 448 + x1];
    float r0 = a * (1.f - ty) + cv * ty;
    float r1 = bv * (1.f - ty) + dv * ty;
    g_x336[idx] = r0 * (1.f - tx) + r1 * tx;
}

// ---------------- weight transpose: W[K,N] -> B[N,Kp] fp16 ----------------
__global__ void weight_halfT(const float* __restrict__ W, int K, int N, int Kp,
                             __half* __restrict__ B) {
    long long idx = (long long)blockIdx.x * blockDim.x + threadIdx.x;
    long long total = (long long)N * Kp;
    if (idx >= total) return;
    int k = (int)(idx % Kp);
    int n = (int)(idx / Kp);
    float v = (k < K) ? W[(long long)k * N + n] : 0.f;
    B[idx] = __float2half_rn(v);
}

// ---------------- weight row-cast (no transpose): W[Kreal,C] -> [Kpad,C] ----
__global__ void weight_cast(const float* __restrict__ W, int Kreal, int Kpad, int C,
                            __half* __restrict__ O) {
    long long idx = (long long)blockIdx.x * blockDim.x + threadIdx.x;
    long long total = (long long)Kpad * C;
    if (idx >= total) return;
    int c = (int)(idx % C);
    int k = (int)(idx / C);
    O[idx] = __float2half_rn((k < Kreal) ? W[(long long)k * C + c] : 0.f);
}

// ---------------- combined bias (block-per-n): bc[n] = bp[n] + bt . wp[:,n] -
__global__ void bias_comb(const float* __restrict__ bt, const float* __restrict__ wp,
                          const float* __restrict__ bp, int C, float* __restrict__ bc) {
    const int n = blockIdx.x;            // 1024 blocks
    const int tid = threadIdx.x;         // 256 threads
    float s = 0.f;
    for (int c = tid; c < C; c += 256) s += bt[c] * wp[(long long)c * 1024 + n];
#pragma unroll
    for (int o = 16; o > 0; o >>= 1) s += __shfl_down_sync(0xFFFFFFFFu, s, o);
    __shared__ float red[8];
    if ((tid & 31) == 0) red[tid >> 5] = s;
    __syncthreads();
    if (tid == 0) {
        float t = 0.f;
#pragma unroll
        for (int i = 0; i < 8; i++) t += red[i];
        bc[n] = t + bp[n];
    }
}

// ---------------- im2col -> fp16 (templated; 8 elems/thread) ----------------
template <int S, int P, int G, int KP>
__global__ void im2col_half(const float* __restrict__ src, const float* __restrict__ gate,
                            __half* __restrict__ A) {
    constexpr int K = 3 * P * P;
    constexpr int GG = G * G;
    long long v8 = (long long)blockIdx.x * blockDim.x + threadIdx.x;
    const long long total8 = 64LL * GG * (KP / 8);
    if (v8 >= total8) return;
    int kc = (int)(v8 % (KP / 8));
    long long row = v8 / (KP / 8);
    int t = (int)(row % GG);
    int b = (int)(row / GG);
    if (gate[b] == 0.f) return;
    const int ty = t / G, tx = t % G;
    const float* sb = src + ((long long)b * 3) * S * S;
    __half h[8];
#pragma unroll
    for (int j = 0; j < 8; j++) {
        int k = kc * 8 + j;
        float v = 0.f;
        if (k < K) {
            int ch = k / (P * P);
            int rr = k - ch * (P * P);
            int py = rr / P, px = rr - py * P;
            v = sb[((long long)ch * S + (ty * P + py)) * S + (tx * P + px)];
        }
        h[j] = __float2half_rn(v);
    }
    *reinterpret_cast<uint4*>(&A[row * KP + kc * 8]) = *reinterpret_cast<uint4*>(h);
}

// ---------------- fused dual gated bilinear combine into out ----------------
// out[b*1024+ot,:] += w1*interp_G1(proj1) + w2*interp_G2(proj2), one RMW sweep.
template <int G1, int G2>
__global__ void resize_combine2(const float* __restrict__ proj1, const float* __restrict__ proj2,
                                const float* __restrict__ gate1, const float* __restrict__ gate2,
                                float* __restrict__ out) {
    long long idx = (long long)blockIdx.x * blockDim.x + threadIdx.x;
    const long long total = 64LL * 1024 * 256;     // float4 granularity
    if (idx >= total) return;
    int cc = (int)(idx & 255);
    long long r = idx >> 8;
    int ot = (int)(r & 1023);
    int b = (int)(r >> 10);
    float w1 = gate1[b], w2 = gate2[b];
    if (w1 == 0.f && w2 == 0.f) return;
    int oy = ot >> 5, ox = ot & 31;
    float4 acc = make_float4(0.f, 0.f, 0.f, 0.f);
    if (w1 != 0.f) {
        const float sc = (float)(G1 - 1) / 31.0f;
        float ys = oy * sc, xs = ox * sc;
        int y0 = (int)floorf(ys); int y1 = min(y0 + 1, G1 - 1);
        int x0 = (int)floorf(xs); int x1 = min(x0 + 1, G1 - 1);
        float ty = ys - (float)y0, tx = xs - (float)x0;
        const float* pb = proj1 + (long long)b * G1 * G1 * 1024 + cc * 4;
        float4 a = *reinterpret_cast<const float4*>(pb + (long long)(y0 * G1 + x0) * 1024);
        float4 bv = *reinterpret_cast<const float4*>(pb + (long long)(y0 * G1 + x1) * 1024);
        float4 cv = *reinterpret_cast<const float4*>(pb + (long long)(y1 * G1 + x0) * 1024);
        float4 dv = *reinterpret_cast<const float4*>(pb + (long long)(y1 * G1 + x1) * 1024);
        float r0, r1;
        r0 = a.x * (1.f - ty) + cv.x * ty; r1 = bv.x * (1.f - ty) + dv.x * ty;
        acc.x += w1 * (r0 * (1.f - tx) + r1 * tx);
        r0 = a.y * (1.f - ty) + cv.y * ty; r1 = bv.y * (1.f - ty) + dv.y * ty;
        acc.y += w1 * (r0 * (1.f - tx) + r1 * tx);
        r0 = a.z * (1.f - ty) + cv.z * ty; r1 = bv.z * (1.f - ty) + dv.z * ty;
        acc.z += w1 * (r0 * (1.f - tx) + r1 * tx);
        r0 = a.w * (1.f - ty) + cv.w * ty; r1 = bv.w * (1.f - ty) + dv.w * ty;
        acc.w += w1 * (r0 * (1.f - tx) + r1 * tx);
    }
    if (w2 != 0.f) {
        const float sc = (float)(G2 - 1) / 31.0f;
        float ys = oy * sc, xs = ox * sc;
        int y0 = (int)floorf(ys); int y1 = min(y0 + 1, G2 - 1);
        int x0 = (int)floorf(xs); int x1 = min(x0 + 1, G2 - 1);
        float ty = ys - (float)y0, tx = xs - (float)x0;
        const float* pb = proj2 + (long long)b * G2 * G2 * 1024 + cc * 4;
        float4 a = *reinterpret_cast<const float4*>(pb + (long long)(y0 * G2 + x0) * 1024);
        float4 bv = *reinterpret_cast<const float4*>(pb + (long long)(y0 * G2 + x1) * 1024);
        float4 cv = *reinterpret_cast<const float4*>(pb + (long long)(y1 * G2 + x0) * 1024);
        float4 dv = *reinterpret_cast<const float4*>(pb + (long long)(y1 * G2 + x1) * 1024);
        float r0, r1;
        r0 = a.x * (1.f - ty) + cv.x * ty; r1 = bv.x * (1.f - ty) + dv.x * ty;
        acc.x += w2 * (r0 * (1.f - tx) + r1 * tx);
        r0 = a.y * (1.f - ty) + cv.y * ty; r1 = bv.y * (1.f - ty) + dv.y * ty;
        acc.y += w2 * (r0 * (1.f - tx) + r1 * tx);
        r0 = a.z * (1.f - ty) + cv.z * ty; r1 = bv.z * (1.f - ty) + dv.z * ty;
        acc.z += w2 * (r0 * (1.f - tx) + r1 * tx);
        r0 = a.w * (1.f - ty) + cv.w * ty; r1 = bv.w * (1.f - ty) + dv.w * ty;
        acc.w += w2 * (r0 * (1.f - tx) + r1 * tx);
    }
    float* op = out + ((long long)(b * 1024 + ot)) * 1024 + cc * 4;
    float4 o = *reinterpret_cast<const float4*>(op);
    o.x += acc.x; o.y += acc.y; o.z += acc.z; o.w += acc.w;
    *reinterpret_cast<float4*>(op) = o;
}

// ---------------- HMMA GEMM: C = A @ B^T, fp32 accumulate ------------------
// 128x128 CTA tile, warp tile 64x32, K-chunk 64, 3-stage cp.async pipeline.
// outmode 0: outF = acc + bias   1: outF += gate*(acc+bias)   2: outH fp16
__global__ void __launch_bounds__(256) gemm_mma(
    const __half* __restrict__ A, const __half* __restrict__ B,
    const float* __restrict__ bias, int N, int Kp,
    const float* __restrict__ gate, int gg, int outmode,
    float* __restrict__ outF, __half* __restrict__ outH)
{
    const int row0 = blockIdx.y * 128;
    const int col0 = blockIdx.x * 128;
    {   // gated tile skip
        int b0 = row0 / gg, b1 = (row0 + 127) / gg;
        float gm = 0.f;
        for (int b = b0; b <= b1; b++) gm = fmaxf(gm, gate[b]);
        if (gm == 0.f) return;
    }

    extern __shared__ char smem[];
    const uint32_t S = smem_u32(smem);
    const int tid = threadIdx.x;
    const int wid = tid >> 5, lane = tid & 31;
    const int wm = (wid >> 2) * 64;
    const int wn = (wid & 3) * 32;
    const int NC = Kp >> 6;

    auto prefetch = [&](int c) {
        uint32_t st = S + (uint32_t)(c % 3) * 32768u;
        int kt = c << 6;
#pragma unroll
        for (int i = 0; i < 8; i++) {
            int cid = tid + (i << 8);
            int isB = cid >> 10;
            int rem = cid & 1023;
            int r = rem >> 3, j = rem & 7;
            const __half* gp = (!isB ? A + (size_t)(row0 + r) * Kp
                                     : B + (size_t)(col0 + r) * Kp) + kt + j * 8;
            uint32_t so = st + (isB << 14) + r * 128 + ((j ^ (r & 7)) << 4);
            cp16(so, gp);
        }
        asm volatile("cp.async.commit_group;" ::: "memory");
    };

    float acc[4][4][4];
#pragma unroll
    for (int i = 0; i < 4; i++)
#pragma unroll
        for (int j = 0; j < 4; j++)
#pragma unroll
            for (int q = 0; q < 4; q++) acc[i][j][q] = 0.f;

    const int lrow = lane & 15;
    const int lchunk = lane >> 4;

    prefetch(0);
    if (NC > 1) prefetch(1);
    for (int c = 0; c < NC; c++) {
        if (c + 2 < NC) {
            prefetch(c + 2);
            asm volatile("cp.async.wait_group 2;" ::: "memory");
        } else if (c + 1 < NC) {
            asm volatile("cp.async.wait_group 1;" ::: "memory");
        } else {
            asm volatile("cp.async.wait_group 0;" ::: "memory");
        }
        __syncthreads();

        uint32_t SA = S + (uint32_t)(c % 3) * 32768u;
        uint32_t SB = SA + 16384u;

#pragma unroll
        for (int k = 0; k < 4; k++) {
            const int ch = 2 * k + lchunk;
            uint32_t b[2][4];
#pragma unroll
            for (int j2 = 0; j2 < 2; j2++) {
                int rb = wn + j2 * 16 + lrow;
                ldm4(b[j2], SB + rb * 128 + ((ch ^ (rb & 7)) << 4));
            }
#pragma unroll
            for (int i = 0; i < 4; i++) {
                int ra = wm + i * 16 + lrow;
                uint32_t a[4];
                ldm4(a, SA + ra * 128 + ((ch ^ (ra & 7)) << 4));
#pragma unroll
                for (int j2 = 0; j2 < 2; j2++) {
                    mma_f16(acc[i][2 * j2],     a, b[j2][0], b[j2][2]);
                    mma_f16(acc[i][2 * j2 + 1], a, b[j2][1], b[j2][3]);
                }
            }
        }
        __syncthreads();
    }

    // ---- epilogue ----
    const int grp = lane >> 2, qid = lane & 3;
#pragma unroll
    for (int i = 0; i < 4; i++) {
        int r0 = row0 + wm + i * 16 + grp;
        int r1 = r0 + 8;
#pragma unroll
        for (int j = 0; j < 4; j++) {
            int col = col0 + wn + j * 8 + qid * 2;
            float b0 = bias[col], b1 = bias[col + 1];
            float v00 = acc[i][j][0] + b0, v01 = acc[i][j][1] + b1;
            float v10 = acc[i][j][2] + b0, v11 = acc[i][j][3] + b1;
            if (outmode == 0) {
                *reinterpret_cast<float2*>(&outF[(size_t)r0 * N + col]) = make_float2(v00, v01);
                *reinterpret_cast<float2*>(&outF[(size_t)r1 * N + col]) = make_float2(v10, v11);
            } else if (outmode == 1) {
                float w0 = gate[r0 / gg], w1 = gate[r1 / gg];
                if (w0 != 0.f) {
                    float2 o = *reinterpret_cast<const float2*>(&outF[(size_t)r0 * N + col]);
                    o.x += w0 * v00; o.y += w0 * v01;
                    *reinterpret_cast<float2*>(&outF[(size_t)r0 * N + col]) = o;
                }
                if (w1 != 0.f) {
                    float2 o = *reinterpret_cast<const float2*>(&outF[(size_t)r1 * N + col]);
                    o.x += w1 * v10; o.y += w1 * v11;
                    *reinterpret_cast<float2*>(&outF[(size_t)r1 * N + col]) = o;
                }
            } else {
                __half2 hp;
                hp.x = __float2half_rn(v00); hp.y = __float2half_rn(v01);
                *reinterpret_cast<__half2*>(&outH[(size_t)r0 * N + col]) = hp;
                hp.x = __float2half_rn(v10); hp.y = __float2half_rn(v11);
                *reinterpret_cast<__half2*>(&outH[(size_t)r1 * N + col]) = hp;
            }
        }
    }
}

// ---------------- launch ----------------
static inline int nblk(long long total, int t) { return (int)((total + t - 1) / t); }

extern "C" void kernel_launch(void* const* d_in, const int* in_sizes, int n_in,
                              void* d_out, int out_size) {
    const float* x   = (const float*)d_in[0];
    const int*   sel = (const int*)d_in[1];
    const float* rw  = (const float*)d_in[2];
    const float* wt0 = (const float*)d_in[3];  const float* bt0 = (const float*)d_in[4];
    const float* wp0 = (const float*)d_in[5];  const float* bp0 = (const float*)d_in[6];
    const float* wt1 = (const float*)d_in[7];  const float* bt1 = (const float*)d_in[8];
    const float* wp1 = (const float*)d_in[9];  const float* bp1 = (const float*)d_in[10];
    const float* wt2 = (const float*)d_in[11]; const float* bt2 = (const float*)d_in[12];
    const float* wp2 = (const float*)d_in[13]; const float* bp2 = (const float*)d_in[14];
    float* out = (float*)d_out;

    float *gate_d, *one_d, *zb_d, *x336_d, *proj1_d, *proj2_d, *bc0_d, *bc1_d, *bc2_d;
    __half *A10, *A11, *A12, *WpT0, *WpT1, *WpT2, *WtC0, *WtC1, *WtC2, *Bc0, *Bc1, *Bc2;
    cudaGetSymbolAddress((void**)&gate_d, g_gate);
    cudaGetSymbolAddress((void**)&one_d, g_one);
    cudaGetSymbolAddress((void**)&zb_d, g_zb);
    cudaGetSymbolAddress((void**)&x336_d, g_x336);
    cudaGetSymbolAddress((void**)&proj1_d, g_proj1);
    cudaGetSymbolAddress((void**)&proj2_d, g_proj2);
    cudaGetSymbolAddress((void**)&bc0_d, g_bc0);
    cudaGetSymbolAddress((void**)&bc1_d, g_bc1);
    cudaGetSymbolAddress((void**)&bc2_d, g_bc2);
    cudaGetSymbolAddress((void**)&A10, g_A1_0);
    cudaGetSymbolAddress((void**)&A11, g_A1_1);
    cudaGetSymbolAddress((void**)&A12, g_A1_2);
    cudaGetSymbolAddress((void**)&WpT0, g_WpT0);
    cudaGetSymbolAddress((void**)&WpT1, g_WpT1);
    cudaGetSymbolAddress((void**)&WpT2, g_WpT2);
    cudaGetSymbolAddress((void**)&WtC0, g_WtC0);
    cudaGetSymbolAddress((void**)&WtC1, g_WtC1);
    cudaGetSymbolAddress((void**)&WtC2, g_WtC2);
    cudaGetSymbolAddress((void**)&Bc0, g_Bc0);
    cudaGetSymbolAddress((void**)&Bc1, g_Bc1);
    cudaGetSymbolAddress((void**)&Bc2, g_Bc2);

    static cudaStream_t s1 = nullptr, s2 = nullptr;
    static cudaEvent_t evG = nullptr, evC0 = nullptr, evP1 = nullptr, evP2 = nullptr;
    if (s1 == nullptr) {
        cudaStreamCreateWithFlags(&s1, cudaStreamNonBlocking);
        cudaStreamCreateWithFlags(&s2, cudaStreamNonBlocking);
        cudaEventCreateWithFlags(&evG, cudaEventDisableTiming);
        cudaEventCreateWithFlags(&evC0, cudaEventDisableTiming);
        cudaEventCreateWithFlags(&evP1, cudaEventDisableTiming);
        cudaEventCreateWithFlags(&evP2, cudaEventDisableTiming);
    }

    const int SMEM = 3 * 32768;
    cudaFuncSetAttribute(gemm_mma, cudaFuncAttributeMaxDynamicSharedMemorySize, SMEM);
    const int BIGG = 1 << 30;

    // ---- main: gates, memset; fork side streams ----
    gate_kernel<<<1, 64>>>(sel, rw);
    cudaEventRecord(evG, 0);
    cudaMemsetAsync(d_out, 0, (size_t)out_size * sizeof(float));

    // ---- s1: e0 combined-weight prep, then e1 chain ----
    cudaStreamWaitEvent(s1, evG, 0);
    weight_halfT<<<nblk(1024LL * 1024, 256), 256, 0, s1>>>(wp0, 1024, 1024, 1024, WpT0);
    weight_cast<<<nblk(640LL * 1024, 256), 256, 0, s1>>>(wt0, 588, 640, 1024, WtC0);
    bias_comb<<<1024, 256, 0, s1>>>(bt0, wp0, bp0, 1024, bc0_d);
    gemm_mma<<<dim3(5, 8), 256, SMEM, s1>>>(WpT0, WtC0, zb_d, 640, 1024,
                                            one_d, BIGG, 2, nullptr, Bc0);
    cudaEventRecord(evC0, s1);
    weight_halfT<<<nblk(1024LL * 768, 256), 256, 0, s1>>>(wp1, 768, 1024, 768, WpT1);
    weight_cast<<<nblk(640LL * 768, 256), 256, 0, s1>>>(wt1, 588, 640, 768, WtC1);
    bias_comb<<<1024, 256, 0, s1>>>(bt1, wp1, bp1, 768, bc1_d);
    gemm_mma<<<dim3(5, 8), 256, SMEM, s1>>>(WpT1, WtC1, zb_d, 640, 768,
                                            one_d, BIGG, 2, nullptr, Bc1);
    resize_input_kernel<<<nblk(64LL * 3 * 336 * 336, 256), 256, 0, s1>>>(x);
    im2col_half<336, 14, 24, 640><<<nblk(64LL * 576 * 80, 256), 256, 0, s1>>>(x336_d, gate_d + 64, A11);
    gemm_mma<<<dim3(8, 288), 256, SMEM, s1>>>(A11, Bc1, bc1_d, 1024, 640,
                                              gate_d + 64, 576, 0, proj1_d, nullptr);
    cudaEventRecord(evP1, s1);

    // ---- s2: e2 chain ----
    cudaStreamWaitEvent(s2, evG, 0);
    weight_halfT<<<nblk(1024LL * 1152, 256), 256, 0, s2>>>(wp2, 1152, 1024, 1152, WpT2);
    weight_cast<<<nblk(3072LL * 1152, 256), 256, 0, s2>>>(wt2, 3072, 3072, 1152, WtC2);
    bias_comb<<<1024, 256, 0, s2>>>(bt2, wp2, bp2, 1152, bc2_d);
    gemm_mma<<<dim3(24, 8), 256, SMEM, s2>>>(WpT2, WtC2, zb_d, 3072, 1152,
                                             one_d, BIGG, 2, nullptr, Bc2);
    im2col_half<448, 32, 14, 3072><<<nblk(64LL * 196 * 384, 256), 256, 0, s2>>>(x, gate_d + 128, A12);
    gemm_mma<<<dim3(8, 98), 256, SMEM, s2>>>(A12, Bc2, bc2_d, 1024, 3072,
                                             gate_d + 128, 196, 0, proj2_d, nullptr);
    cudaEventRecord(evP2, s2);

    // ---- main: e0 single GEMM into out, then fused combine ----
    im2col_half<448, 14, 32, 640><<<nblk(64LL * 1024 * 80, 256), 256>>>(x, gate_d, A10);
    cudaStreamWaitEvent(0, evC0, 0);
    gemm_mma<<<dim3(8, 512), 256, SMEM>>>(A10, Bc0, bc0_d, 1024, 640,
                                          gate_d, 1024, 1, out, nullptr);
    cudaStreamWaitEvent(0, evP1, 0);
    cudaStreamWaitEvent(0, evP2, 0);
    resize_combine2<24, 14><<<nblk(64LL * 1024 * 256, 256), 256>>>(
        proj1_d, proj2_d, gate_d + 64, gate_d + 128, out);
}

// round 16
// speedup vs baseline: 1.0021x; 1.0015x over previous
#include <cuda_runtime.h>
#include <cuda_fp16.h>
#include <cstdint>
#include <math.h>

// ============================================================================
// VisionExperts, Round 11: R10 linear collapse +
//  (1) parallel bias_comb (block-per-n reduction; was 79us x3 serial),
//  (2) fused dual resize_combine (one RMW sweep of out instead of two),
//  (3) e2 chain on its own stream (s2) concurrent with e1 chain (s1).
// ============================================================================

// ---------------- scratch (device globals; no allocs) ----------------
__device__ float g_gate[3 * 64];
__device__ float g_one[1];
__device__ float g_zb[3072];                          // zero bias (static zero-init)
__device__ float g_x336[21676032];
__device__ float g_proj1[37748736];                   // e1 projected (36864x1024)
__device__ float g_proj2[12845056];                   // e2 projected (12544x1024)
__device__ float g_bc0[1024], g_bc1[1024], g_bc2[1024];
__device__ __align__(128) __half g_A1_0[41943040];    // 65536 x 640
__device__ __align__(128) __half g_A1_1[23592960];    // 36864 x 640
__device__ __align__(128) __half g_A1_2[38535168];    // 12544 x 3072
__device__ __align__(128) __half g_WpT0[1048576];     // 1024 x 1024
__device__ __align__(128) __half g_WpT1[786432];      // 1024 x 768
__device__ __align__(128) __half g_WpT2[1179648];     // 1024 x 1152
__device__ __align__(128) __half g_WtC0[655360];      // 640 x 1024
__device__ __align__(128) __half g_WtC1[491520];      // 640 x 768
__device__ __align__(128) __half g_WtC2[3538944];     // 3072 x 1152
__device__ __align__(128) __half g_Bc0[655360];       // Bcomb0: 1024 x 640
__device__ __align__(128) __half g_Bc1[655360];       // Bcomb1: 1024 x 640
__device__ __align__(128) __half g_Bc2[3145728];      // Bcomb2: 1024 x 3072

// ---------------- helpers ----------------
__device__ __forceinline__ uint32_t smem_u32(const void* p) {
    uint32_t a;
    asm("{ .reg .u64 t; cvta.to.shared.u64 t, %1; cvt.u32.u64 %0, t; }" : "=r"(a) : "l"(p));
    return a;
}
__device__ __forceinline__ void cp16(uint32_t so, const void* g) {
    asm volatile("cp.async.cg.shared.global [%0], [%1], 16;" :: "r"(so), "l"(g));
}
__device__ __forceinline__ void ldm4(uint32_t* r, uint32_t addr) {
    asm volatile("ldmatrix.sync.aligned.m8n8.x4.shared.b16 {%0,%1,%2,%3}, [%4];"
                 : "=r"(r[0]), "=r"(r[1]), "=r"(r[2]), "=r"(r[3]) : "r"(addr));
}
__device__ __forceinline__ void mma_f16(float* d, const uint32_t* a, uint32_t b0, uint32_t b1) {
    asm volatile("mma.sync.aligned.m16n8k16.row.col.f32.f16.f16.f32 "
                 "{%0,%1,%2,%3}, {%4,%5,%6,%7}, {%8,%9}, {%0,%1,%2,%3};"
                 : "+f"(d[0]), "+f"(d[1]), "+f"(d[2]), "+f"(d[3])
                 : "r"(a[0]), "r"(a[1]), "r"(a[2]), "r"(a[3]), "r"(b0), "r"(b1));
}

// ---------------- gates ----------------
__global__ void gate_kernel(const int* __restrict__ sel, const float* __restrict__ rw) {
    int b = threadIdx.x;
    if (b == 0) g_one[0] = 1.f;
    if (b >= 64) return;
    float w0 = 0.f, w1 = 0.f, w2 = 0.f;
#pragma unroll
    for (int k = 0; k < 2; k++) {
        int e = sel[b * 2 + k];
        float r = rw[b * 2 + k];
        w0 += (e == 0) ? r : 0.f;
        w1 += (e == 1) ? r : 0.f;
        w2 += (e == 2) ? r : 0.f;
    }
    g_gate[b] = w0; g_gate[64 + b] = w1; g_gate[128 + b] = w2;
}

// ---------------- input resize 448 -> 336 ----------------
__global__ void resize_input_kernel(const float* __restrict__ x) {
    long long idx = (long long)blockIdx.x * blockDim.x + threadIdx.x;
    const long long total = 64LL * 3 * 336 * 336;
    if (idx >= total) return;
    int ox = (int)(idx % 336);
    long long r = idx / 336;
    int oy = (int)(r % 336); r /= 336;
    int c = (int)(r % 3);
    int b = (int)(r / 3);
    if (g_gate[64 + b] == 0.f) return;
    const float sc = 447.0f / 335.0f;
    float ys = oy * sc, xs = ox * sc;
    int y0 = (int)floorf(ys); int y1 = min(y0 + 1, 447);
    int x0 = (int)floorf(xs); int x1 = min(x0 + 1, 447);
    float ty = ys - (float)y0, tx = xs - (float)x0;
    const float* p = x + ((long long)(b * 3 + c)) * 448 * 448;
    float a = p[y0 * 448 + x0], bv = p[y0 * 448 + x1];
    float cv = p[y1 * 448 + x0], dv = p[y1 * 448 + x1];
    float r0 = a * (1.f - ty) + cv * ty;
    float r1 = bv * (1.f - ty) + dv * ty;
    g_x336[idx] = r0 * (1.f - tx) + r1 * tx;
}

// ---------------- weight transpose: W[K,N] -> B[N,Kp] fp16 ----------------
__global__ void weight_halfT(const float* __restrict__ W, int K, int N, int Kp,
                             __half* __restrict__ B) {
    long long idx = (long long)blockIdx.x * blockDim.x + threadIdx.x;
    long long total = (long long)N * Kp;
    if (idx >= total) return;
    int k = (int)(idx % Kp);
    int n = (int)(idx / Kp);
    float v = (k < K) ? W[(long long)k * N + n] : 0.f;
    B[idx] = __float2half_rn(v);
}

// ---------------- weight row-cast (no transpose): W[Kreal,C] -> [Kpad,C] ----
__global__ void weight_cast(const float* __restrict__ W, int Kreal, int Kpad, int C,
                            __half* __restrict__ O) {
    long long idx = (long long)blockIdx.x * blockDim.x + threadIdx.x;
    long long total = (long long)Kpad * C;
    if (idx >= total) return;
    int c = (int)(idx % C);
    int k = (int)(idx / C);
    O[idx] = __float2half_rn((k < Kreal) ? W[(long long)k * C + c] : 0.f);
}

// ---------------- combined bias (block-per-n): bc[n] = bp[n] + bt . wp[:,n] -
__global__ void bias_comb(const float* __restrict__ bt, const float* __restrict__ wp,
                          const float* __restrict__ bp, int C, float* __restrict__ bc) {
    const int n = blockIdx.x;            // 1024 blocks
    const int tid = threadIdx.x;         // 256 threads
    float s = 0.f;
    for (int c = tid; c < C; c += 256) s += bt[c] * wp[(long long)c * 1024 + n];
#pragma unroll
    for (int o = 16; o > 0; o >>= 1) s += __shfl_down_sync(0xFFFFFFFFu, s, o);
    __shared__ float red[8];
    if ((tid & 31) == 0) red[tid >> 5] = s;
    __syncthreads();
    if (tid == 0) {
        float t = 0.f;
#pragma unroll
        for (int i = 0; i < 8; i++) t += red[i];
        bc[n] = t + bp[n];
    }
}

// ---------------- im2col -> fp16 (templated; 8 elems/thread) ----------------
template <int S, int P, int G, int KP>
__global__ void im2col_half(const float* __restrict__ src, const float* __restrict__ gate,
                            __half* __restrict__ A) {
    constexpr int K = 3 * P * P;
    constexpr int GG = G * G;
    long long v8 = (long long)blockIdx.x * blockDim.x + threadIdx.x;
    const long long total8 = 64LL * GG * (KP / 8);
    if (v8 >= total8) return;
    int kc = (int)(v8 % (KP / 8));
    long long row = v8 / (KP / 8);
    int t = (int)(row % GG);
    int b = (int)(row / GG);
    if (gate[b] == 0.f) return;
    const int ty = t / G, tx = t % G;
    const float* sb = src + ((long long)b * 3) * S * S;
    __half h[8];
#pragma unroll
    for (int j = 0; j < 8; j++) {
        int k = kc * 8 + j;
        float v = 0.f;
        if (k < K) {
            int ch = k / (P * P);
            int rr = k - ch * (P * P);
            int py = rr / P, px = rr - py * P;
            v = sb[((long long)ch * S + (ty * P + py)) * S + (tx * P + px)];
        }
        h[j] = __float2half_rn(v);
    }
    *reinterpret_cast<uint4*>(&A[row * KP + kc * 8]) = *reinterpret_cast<uint4*>(h);
}

// ---------------- fused dual gated bilinear combine into out ----------------
// out[b*1024+ot,:] += w1*interp_G1(proj1) + w2*interp_G2(proj2), one RMW sweep.
template <int G1, int G2>
__global__ void resize_combine2(const float* __restrict__ proj1, const float* __restrict__ proj2,
                                const float* __restrict__ gate1, const float* __restrict__ gate2,
                                float* __restrict__ out) {
    long long idx = (long long)blockIdx.x * blockDim.x + threadIdx.x;
    const long long total = 64LL * 1024 * 256;     // float4 granularity
    if (idx >= total) return;
    int cc = (int)(idx & 255);
    long long r = idx >> 8;
    int ot = (int)(r & 1023);
    int b = (int)(r >> 10);
    float w1 = gate1[b], w2 = gate2[b];
    if (w1 == 0.f && w2 == 0.f) return;
    int oy = ot >> 5, ox = ot & 31;
    float4 acc = make_float4(0.f, 0.f, 0.f, 0.f);
    if (w1 != 0.f) {
        const float sc = (float)(G1 - 1) / 31.0f;
        float ys = oy * sc, xs = ox * sc;
        int y0 = (int)floorf(ys); int y1 = min(y0 + 1, G1 - 1);
        int x0 = (int)floorf(xs); int x1 = min(x0 + 1, G1 - 1);
        float ty = ys - (float)y0, tx = xs - (float)x0;
        const float* pb = proj1 + (long long)b * G1 * G1 * 1024 + cc * 4;
        float4 a = *reinterpret_cast<const float4*>(pb + (long long)(y0 * G1 + x0) * 1024);
        float4 bv = *reinterpret_cast<const float4*>(pb + (long long)(y0 * G1 + x1) * 1024);
        float4 cv = *reinterpret_cast<const float4*>(pb + (long long)(y1 * G1 + x0) * 1024);
        float4 dv = *reinterpret_cast<const float4*>(pb + (long long)(y1 * G1 + x1) * 1024);
        float r0, r1;
        r0 = a.x * (1.f - ty) + cv.x * ty; r1 = bv.x * (1.f - ty) + dv.x * ty;
        acc.x += w1 * (r0 * (1.f - tx) + r1 * tx);
        r0 = a.y * (1.f - ty) + cv.y * ty; r1 = bv.y * (1.f - ty) + dv.y * ty;
        acc.y += w1 * (r0 * (1.f - tx) + r1 * tx);
        r0 = a.z * (1.f - ty) + cv.z * ty; r1 = bv.z * (1.f - ty) + dv.z * ty;
        acc.z += w1 * (r0 * (1.f - tx) + r1 * tx);
        r0 = a.w * (1.f - ty) + cv.w * ty; r1 = bv.w * (1.f - ty) + dv.w * ty;
        acc.w += w1 * (r0 * (1.f - tx) + r1 * tx);
    }
    if (w2 != 0.f) {
        const float sc = (float)(G2 - 1) / 31.0f;
        float ys = oy * sc, xs = ox * sc;
        int y0 = (int)floorf(ys); int y1 = min(y0 + 1, G2 - 1);
        int x0 = (int)floorf(xs); int x1 = min(x0 + 1, G2 - 1);
        float ty = ys - (float)y0, tx = xs - (float)x0;
        const float* pb = proj2 + (long long)b * G2 * G2 * 1024 + cc * 4;
        float4 a = *reinterpret_cast<const float4*>(pb + (long long)(y0 * G2 + x0) * 1024);
        float4 bv = *reinterpret_cast<const float4*>(pb + (long long)(y0 * G2 + x1) * 1024);
        float4 cv = *reinterpret_cast<const float4*>(pb + (long long)(y1 * G2 + x0) * 1024);
        float4 dv = *reinterpret_cast<const float4*>(pb + (long long)(y1 * G2 + x1) * 1024);
        float r0, r1;
        r0 = a.x * (1.f - ty) + cv.x * ty; r1 = bv.x * (1.f - ty) + dv.x * ty;
        acc.x += w2 * (r0 * (1.f - tx) + r1 * tx);
        r0 = a.y * (1.f - ty) + cv.y * ty; r1 = bv.y * (1.f - ty) + dv.y * ty;
        acc.y += w2 * (r0 * (1.f - tx) + r1 * tx);
        r0 = a.z * (1.f - ty) + cv.z * ty; r1 = bv.z * (1.f - ty) + dv.z * ty;
        acc.z += w2 * (r0 * (1.f - tx) + r1 * tx);
        r0 = a.w * (1.f - ty) + cv.w * ty; r1 = bv.w * (1.f - ty) + dv.w * ty;
        acc.w += w2 * (r0 * (1.f - tx) + r1 * tx);
    }
    float* op = out + ((long long)(b * 1024 + ot)) * 1024 + cc * 4;
    float4 o = *reinterpret_cast<const float4*>(op);
    o.x += acc.x; o.y += acc.y; o.z += acc.z; o.w += acc.w;
    *reinterpret_cast<float4*>(op) = o;
}

// ---------------- HMMA GEMM: C = A @ B^T, fp32 accumulate ------------------
// 128x128 CTA tile, warp tile 64x32, K-chunk 64, 3-stage cp.async pipeline.
// outmode 0: outF = acc + bias   1: outF += gate*(acc+bias)   2: outH fp16
__global__ void __launch_bounds__(256) gemm_mma(
    const __half* __restrict__ A, const __half* __restrict__ B,
    const float* __restrict__ bias, int N, int Kp,
    const float* __restrict__ gate, int gg, int outmode,
    float* __restrict__ outF, __half* __restrict__ outH)
{
    const int row0 = blockIdx.y * 128;
    const int col0 = blockIdx.x * 128;
    {   // gated tile skip
        int b0 = row0 / gg, b1 = (row0 + 127) / gg;
        float gm = 0.f;
        for (int b = b0; b <= b1; b++) gm = fmaxf(gm, gate[b]);
        if (gm == 0.f) return;
    }

    extern __shared__ char smem[];
    const uint32_t S = smem_u32(smem);
    const int tid = threadIdx.x;
    const int wid = tid >> 5, lane = tid & 31;
    const int wm = (wid >> 2) * 64;
    const int wn = (wid & 3) * 32;
    const int NC = Kp >> 6;

    auto prefetch = [&](int c) {
        uint32_t st = S + (uint32_t)(c % 3) * 32768u;
        int kt = c << 6;
#pragma unroll
        for (int i = 0; i < 8; i++) {
            int cid = tid + (i << 8);
            int isB = cid >> 10;
            int rem = cid & 1023;
            int r = rem >> 3, j = rem & 7;
            const __half* gp = (!isB ? A + (size_t)(row0 + r) * Kp
                                     : B + (size_t)(col0 + r) * Kp) + kt + j * 8;
            uint32_t so = st + (isB << 14) + r * 128 + ((j ^ (r & 7)) << 4);
            cp16(so, gp);
        }
        asm volatile("cp.async.commit_group;" ::: "memory");
    };

    float acc[4][4][4];
#pragma unroll
    for (int i = 0; i < 4; i++)
#pragma unroll
        for (int j = 0; j < 4; j++)
#pragma unroll
            for (int q = 0; q < 4; q++) acc[i][j][q] = 0.f;

    const int lrow = lane & 15;
    const int lchunk = lane >> 4;

    prefetch(0);
    if (NC > 1) prefetch(1);
    for (int c = 0; c < NC; c++) {
        if (c + 2 < NC) {
            prefetch(c + 2);
            asm volatile("cp.async.wait_group 2;" ::: "memory");
        } else if (c + 1 < NC) {
            asm volatile("cp.async.wait_group 1;" ::: "memory");
        } else {
            asm volatile("cp.async.wait_group 0;" ::: "memory");
        }
        __syncthreads();

        uint32_t SA = S + (uint32_t)(c % 3) * 32768u;
        uint32_t SB = SA + 16384u;

#pragma unroll
        for (int k = 0; k < 4; k++) {
            const int ch = 2 * k + lchunk;
            uint32_t b[2][4];
#pragma unroll
            for (int j2 = 0; j2 < 2; j2++) {
                int rb = wn + j2 * 16 + lrow;
                ldm4(b[j2], SB + rb * 128 + ((ch ^ (rb & 7)) << 4));
            }
#pragma unroll
            for (int i = 0; i < 4; i++) {
                int ra = wm + i * 16 + lrow;
                uint32_t a[4];
                ldm4(a, SA + ra * 128 + ((ch ^ (ra & 7)) << 4));
#pragma unroll
                for (int j2 = 0; j2 < 2; j2++) {
                    mma_f16(acc[i][2 * j2],     a, b[j2][0], b[j2][2]);
                    mma_f16(acc[i][2 * j2 + 1], a, b[j2][1], b[j2][3]);
                }
            }
        }
        __syncthreads();
    }

    // ---- epilogue ----
    const int grp = lane >> 2, qid = lane & 3;
#pragma unroll
    for (int i = 0; i < 4; i++) {
        int r0 = row0 + wm + i * 16 + grp;
        int r1 = r0 + 8;
#pragma unroll
        for (int j = 0; j < 4; j++) {
            int col = col0 + wn + j * 8 + qid * 2;
            float b0 = bias[col], b1 = bias[col + 1];
            float v00 = acc[i][j][0] + b0, v01 = acc[i][j][1] + b1;
            float v10 = acc[i][j][2] + b0, v11 = acc[i][j][3] + b1;
            if (outmode == 0) {
                *reinterpret_cast<float2*>(&outF[(size_t)r0 * N + col]) = make_float2(v00, v01);
                *reinterpret_cast<float2*>(&outF[(size_t)r1 * N + col]) = make_float2(v10, v11);
            } else if (outmode == 1) {
                float w0 = gate[r0 / gg], w1 = gate[r1 / gg];
                if (w0 != 0.f) {
                    float2 o = *reinterpret_cast<const float2*>(&outF[(size_t)r0 * N + col]);
                    o.x += w0 * v00; o.y += w0 * v01;
                    *reinterpret_cast<float2*>(&outF[(size_t)r0 * N + col]) = o;
                }
                if (w1 != 0.f) {
                    float2 o = *reinterpret_cast<const float2*>(&outF[(size_t)r1 * N + col]);
                    o.x += w1 * v10; o.y += w1 * v11;
                    *reinterpret_cast<float2*>(&outF[(size_t)r1 * N + col]) = o;
                }
            } else {
                __half2 hp;
                hp.x = __float2half_rn(v00); hp.y = __float2half_rn(v01);
                *reinterpret_cast<__half2*>(&outH[(size_t)r0 * N + col]) = hp;
                hp.x = __float2half_rn(v10); hp.y = __float2half_rn(v11);
                *reinterpret_cast<__half2*>(&outH[(size_t)r1 * N + col]) = hp;
            }
        }
    }
}

// ---------------- launch ----------------
static inline int nblk(long long total, int t) { return (int)((total + t - 1) / t); }

extern "C" void kernel_launch(void* const* d_in, const int* in_sizes, int n_in,
                              void* d_out, int out_size) {
    const float* x   = (const float*)d_in[0];
    const int*   sel = (const int*)d_in[1];
    const float* rw  = (const float*)d_in[2];
    const float* wt0 = (const float*)d_in[3];  const float* bt0 = (const float*)d_in[4];
    const float* wp0 = (const float*)d_in[5];  const float* bp0 = (const float*)d_in[6];
    const float* wt1 = (const float*)d_in[7];  const float* bt1 = (const float*)d_in[8];
    const float* wp1 = (const float*)d_in[9];  const float* bp1 = (const float*)d_in[10];
    const float* wt2 = (const float*)d_in[11]; const float* bt2 = (const float*)d_in[12];
    const float* wp2 = (const float*)d_in[13]; const float* bp2 = (const float*)d_in[14];
    float* out = (float*)d_out;

    float *gate_d, *one_d, *zb_d, *x336_d, *proj1_d, *proj2_d, *bc0_d, *bc1_d, *bc2_d;
    __half *A10, *A11, *A12, *WpT0, *WpT1, *WpT2, *WtC0, *WtC1, *WtC2, *Bc0, *Bc1, *Bc2;
    cudaGetSymbolAddress((void**)&gate_d, g_gate);
    cudaGetSymbolAddress((void**)&one_d, g_one);
    cudaGetSymbolAddress((void**)&zb_d, g_zb);
    cudaGetSymbolAddress((void**)&x336_d, g_x336);
    cudaGetSymbolAddress((void**)&proj1_d, g_proj1);
    cudaGetSymbolAddress((void**)&proj2_d, g_proj2);
    cudaGetSymbolAddress((void**)&bc0_d, g_bc0);
    cudaGetSymbolAddress((void**)&bc1_d, g_bc1);
    cudaGetSymbolAddress((void**)&bc2_d, g_bc2);
    cudaGetSymbolAddress((void**)&A10, g_A1_0);
    cudaGetSymbolAddress((void**)&A11, g_A1_1);
    cudaGetSymbolAddress((void**)&A12, g_A1_2);
    cudaGetSymbolAddress((void**)&WpT0, g_WpT0);
    cudaGetSymbolAddress((void**)&WpT1, g_WpT1);
    cudaGetSymbolAddress((void**)&WpT2, g_WpT2);
    cudaGetSymbolAddress((void**)&WtC0, g_WtC0);
    cudaGetSymbolAddress((void**)&WtC1, g_WtC1);
    cudaGetSymbolAddress((void**)&WtC2, g_WtC2);
    cudaGetSymbolAddress((void**)&Bc0, g_Bc0);
    cudaGetSymbolAddress((void**)&Bc1, g_Bc1);
    cudaGetSymbolAddress((void**)&Bc2, g_Bc2);

    static cudaStream_t s1 = nullptr, s2 = nullptr;
    static cudaEvent_t evG = nullptr, evC0 = nullptr, evP1 = nullptr, evP2 = nullptr;
    if (s1 == nullptr) {
        cudaStreamCreateWithFlags(&s1, cudaStreamNonBlocking);
        cudaStreamCreateWithFlags(&s2, cudaStreamNonBlocking);
        cudaEventCreateWithFlags(&evG, cudaEventDisableTiming);
        cudaEventCreateWithFlags(&evC0, cudaEventDisableTiming);
        cudaEventCreateWithFlags(&evP1, cudaEventDisableTiming);
        cudaEventCreateWithFlags(&evP2, cudaEventDisableTiming);
    }

    const int SMEM = 3 * 32768;
    cudaFuncSetAttribute(gemm_mma, cudaFuncAttributeMaxDynamicSharedMemorySize, SMEM);
    const int BIGG = 1 << 30;

    // ---- main: gates, memset; fork side streams ----
    gate_kernel<<<1, 64>>>(sel, rw);
    cudaEventRecord(evG, 0);
    cudaMemsetAsync(d_out, 0, (size_t)out_size * sizeof(float));

    // ---- s1: e0 combined-weight prep, then e1 chain ----
    cudaStreamWaitEvent(s1, evG, 0);
    weight_halfT<<<nblk(1024LL * 1024, 256), 256, 0, s1>>>(wp0, 1024, 1024, 1024, WpT0);
    weight_cast<<<nblk(640LL * 1024, 256), 256, 0, s1>>>(wt0, 588, 640, 1024, WtC0);
    bias_comb<<<1024, 256, 0, s1>>>(bt0, wp0, bp0, 1024, bc0_d);
    gemm_mma<<<dim3(5, 8), 256, SMEM, s1>>>(WpT0, WtC0, zb_d, 640, 1024,
                                            one_d, BIGG, 2, nullptr, Bc0);
    cudaEventRecord(evC0, s1);
    weight_halfT<<<nblk(1024LL * 768, 256), 256, 0, s1>>>(wp1, 768, 1024, 768, WpT1);
    weight_cast<<<nblk(640LL * 768, 256), 256, 0, s1>>>(wt1, 588, 640, 768, WtC1);
    bias_comb<<<1024, 256, 0, s1>>>(bt1, wp1, bp1, 768, bc1_d);
    gemm_mma<<<dim3(5, 8), 256, SMEM, s1>>>(WpT1, WtC1, zb_d, 640, 768,
                                            one_d, BIGG, 2, nullptr, Bc1);
    resize_input_kernel<<<nblk(64LL * 3 * 336 * 336, 256), 256, 0, s1>>>(x);
    im2col_half<336, 14, 24, 640><<<nblk(64LL * 576 * 80, 256), 256, 0, s1>>>(x336_d, gate_d + 64, A11);
    gemm_mma<<<dim3(8, 288), 256, SMEM, s1>>>(A11, Bc1, bc1_d, 1024, 640,
                                              gate_d + 64, 576, 0, proj1_d, nullptr);
    cudaEventRecord(evP1, s1);

    // ---- s2: e2 chain ----
    cudaStreamWaitEvent(s2, evG, 0);
    weight_halfT<<<nblk(1024LL * 1152, 256), 256, 0, s2>>>(wp2, 1152, 1024, 1152, WpT2);
    weight_cast<<<nblk(3072LL * 1152, 256), 256, 0, s2>>>(wt2, 3072, 3072, 1152, WtC2);
    bias_comb<<<1024, 256, 0, s2>>>(bt2, wp2, bp2, 1152, bc2_d);
    gemm_mma<<<dim3(24, 8), 256, SMEM, s2>>>(WpT2, WtC2, zb_d, 3072, 1152,
                                             one_d, BIGG, 2, nullptr, Bc2);
    im2col_half<448, 32, 14, 3072><<<nblk(64LL * 196 * 384, 256), 256, 0, s2>>>(x, gate_d + 128, A12);
    gemm_mma<<<dim3(8, 98), 256, SMEM, s2>>>(A12, Bc2, bc2_d, 1024, 3072,
                                             gate_d + 128, 196, 0, proj2_d, nullptr);
    cudaEventRecord(evP2, s2);

    // ---- main: e0 single GEMM into out, then fused combine ----
    im2col_half<448, 14, 32, 640><<<nblk(64LL * 1024 * 80, 256), 256>>>(x, gate_d, A10);
    cudaStreamWaitEvent(0, evC0, 0);
    gemm_mma<<<dim3(8, 512), 256, SMEM>>>(A10, Bc0, bc0_d, 1024, 640,
                                          gate_d, 1024, 1, out, nullptr);
    cudaStreamWaitEvent(0, evP1, 0);
    cudaStreamWaitEvent(0, evP2, 0);
    resize_combine2<24, 14><<<nblk(64LL * 1024 * 256, 256), 256>>>(
        proj1_d, proj2_d, gate_d + 64, gate_d + 128, out);
}